// round 13
// baseline (speedup 1.0000x reference)
#include <cuda_runtime.h>
#include <cuda_fp16.h>
#include <mma.h>
#include <cstdint>

using namespace nvcuda;

#define N_NODES 50000
#define M_PAD 50048
#define N_EDGES 800000
#define D 256
#define K2 512
#define NL 3
#define BN_EPS 1e-5f

// ---------------- device scratch ----------------
// Cross-call invariants: g_deg == 0 at k_scan_scat entry (module-load zero on
// first call; scan re-zeroes after consuming); g_flag reset by k_count.
// g_sums slot (l+2)%3 fully re-zeroed by k_agg(l) block 0 after its last
// reader retired in stream order.
__device__ int    g_deg[N_NODES];
__device__ int    g_rowptr[N_NODES + 1];
__device__ int    g_cursor[N_NODES];
__device__ int    g_csr[N_EDGES];
__device__ volatile int g_flag;
__device__ __half g_x0h[(size_t)M_PAD * D];
__device__ __half g_xah[(size_t)M_PAD * D];
__device__ __half g_xbh[(size_t)M_PAD * D];
__device__ __half g_aggh[(size_t)M_PAD * D];
__device__ __half g_WTh[(size_t)NL * D * K2]; // [layer][n][k] B^T, K-major, fp16
__device__ __half g_h16[(size_t)M_PAD * D];   // pre-BN activations (fp16)
__device__ float  g_sums[NL][2 * D];

// ---------------- helpers ----------------
__device__ __forceinline__ uint32_t smem_u32(const void* p) {
    uint32_t a;
    asm("{ .reg .u64 t; cvta.to.shared.u64 t, %1; cvt.u32.u64 %0, t; }"
        : "=r"(a) : "l"(p));
    return a;
}

__device__ __forceinline__ void cp16(uint32_t dst, const void* src, bool valid) {
    int sz = valid ? 16 : 0;   // sz=0 -> 16-byte zero-fill
    asm volatile("cp.async.cg.shared.global [%0], [%1], 16, %2;"
                 :: "r"(dst), "l"(src), "r"(sz) : "memory");
}

__device__ __forceinline__ void acc8(float* ac, uint4 u) {
    __half2* hp = (__half2*)&u;
    #pragma unroll
    for (int j = 0; j < 4; j++) {
        float2 f = __half22float2(hp[j]);
        ac[2 * j] += f.x;
        ac[2 * j + 1] += f.y;
    }
}

// ---------------- CSR: count (also resets spin flag) ----------------
__global__ void k_count(const int* __restrict__ dst) {
    if (blockIdx.x == 0 && threadIdx.x == 0) g_flag = 0;
    int e = blockIdx.x * blockDim.x + threadIdx.x;
    if (e < N_EDGES) {
        int d = dst[e];
        if (d >= 0 && d < N_NODES) atomicAdd(&g_deg[d], 1);
    }
}

// ---------------- scan (block 0) + spin gate + scatter + cast + transpose ----------------
#define SCAN_C 49
__global__ void __launch_bounds__(1024)
k_scan_scat(const int* __restrict__ src, const int* __restrict__ dst,
            const float* __restrict__ x,
            const float* __restrict__ Wl, const float* __restrict__ Wr) {
    int t = threadIdx.x;
    if (blockIdx.x == 0) {
        int lane = t & 31, w = t >> 5;
        int base = t * SCAN_C;
        int lim = min(base + SCAN_C, N_NODES);
        int sum = 0;
        for (int i = base; i < lim; i++) sum += g_deg[i];
        int v = sum;
        #pragma unroll
        for (int o = 1; o < 32; o <<= 1) {
            int n = __shfl_up_sync(0xffffffffu, v, o);
            if (lane >= o) v += n;
        }
        __shared__ int wt[32];
        if (lane == 31) wt[w] = v;
        __syncthreads();
        if (w == 0) {
            int xv = wt[lane];
            #pragma unroll
            for (int o = 1; o < 32; o <<= 1) {
                int n = __shfl_up_sync(0xffffffffu, xv, o);
                if (lane >= o) xv += n;
            }
            wt[lane] = xv;
        }
        __syncthreads();
        int excl = v - sum + (w > 0 ? wt[w - 1] : 0);
        int run = excl;
        for (int i = base; i < lim; i++) {
            int d = g_deg[i];
            g_rowptr[i] = run;
            g_cursor[i] = run;
            run += d;
            g_deg[i] = 0;
        }
        if (t == 1023) g_rowptr[N_NODES] = run;
        __threadfence();
        __syncthreads();
        if (t == 0) g_flag = 1;
    } else {
        if (t == 0) {
            while (g_flag == 0) __nanosleep(100);
        }
    }
    __syncthreads();
    __threadfence();

    int gtid = blockIdx.x * 1024 + t;
    int stride = gridDim.x * 1024;
    if (gtid < N_EDGES) {
        int d = dst[gtid];
        int sv = src[gtid];
        if (d >= 0 && d < N_NODES && sv >= 0 && sv < N_NODES) {
            int pos = atomicAdd(&g_cursor[d], 1);
            g_csr[pos] = sv;
        }
    }
    const float4* xp = (const float4*)x;
    for (int i = gtid; i < N_NODES * D / 8; i += stride) {
        float4 a = xp[2 * i], b = xp[2 * i + 1];
        __half2 h0 = __floats2half2_rn(a.x, a.y);
        __half2 h1 = __floats2half2_rn(a.z, a.w);
        __half2 h2 = __floats2half2_rn(b.x, b.y);
        __half2 h3 = __floats2half2_rn(b.z, b.w);
        uint4 o;
        o.x = *(uint32_t*)&h0; o.y = *(uint32_t*)&h1;
        o.z = *(uint32_t*)&h2; o.w = *(uint32_t*)&h3;
        ((uint4*)g_x0h)[i] = o;
    }
    for (int i = gtid; i < NL * D * K2; i += stride) {
        int l = i / (D * K2);
        int r = i % (D * K2);
        int n = r / K2, k = r % K2;
        float v = (k < D) ? Wl[(size_t)l * D * D + (size_t)k * D + n]
                          : Wr[(size_t)l * D * D + (size_t)(k - D) * D + n];
        g_WTh[i] = __float2half(v);
    }
}

// ---------------- mean aggregation: one WARP per node, edge-unroll 4 ----------------
__global__ void __launch_bounds__(256)
k_agg(int sel, int layer) {
    const __half* __restrict__ xcur =
        (sel < 0) ? g_x0h : (sel == 0 ? g_xah : g_xbh);
    const int tid = threadIdx.x;
    const int wid = tid >> 5, lid = tid & 31;

    if (blockIdx.x == 0) {
        g_sums[(layer + 2) % NL][tid] = 0.f;
        g_sums[(layer + 2) % NL][tid + 256] = 0.f;
    }

    int node = blockIdx.x * 8 + wid;
    if (node >= N_NODES) return;
    int beg = g_rowptr[node], end = g_rowptr[node + 1];
    float ac[8] = {0.f, 0.f, 0.f, 0.f, 0.f, 0.f, 0.f, 0.f};
    int e = beg;
    for (; e + 3 < end; e += 4) {
        int s0 = g_csr[e], s1 = g_csr[e + 1], s2 = g_csr[e + 2], s3 = g_csr[e + 3];
        uint4 u0 = ((const uint4*)(xcur + (size_t)s0 * D))[lid];
        uint4 u1 = ((const uint4*)(xcur + (size_t)s1 * D))[lid];
        uint4 u2 = ((const uint4*)(xcur + (size_t)s2 * D))[lid];
        uint4 u3 = ((const uint4*)(xcur + (size_t)s3 * D))[lid];
        acc8(ac, u0); acc8(ac, u1); acc8(ac, u2); acc8(ac, u3);
    }
    for (; e < end; e++) {
        uint4 u = ((const uint4*)(xcur + (size_t)g_csr[e] * D))[lid];
        acc8(ac, u);
    }
    float inv = 1.0f / fmaxf((float)(end - beg), 1.0f);
    __half2 h0 = __floats2half2_rn(ac[0] * inv, ac[1] * inv);
    __half2 h1 = __floats2half2_rn(ac[2] * inv, ac[3] * inv);
    __half2 h2 = __floats2half2_rn(ac[4] * inv, ac[5] * inv);
    __half2 h3 = __floats2half2_rn(ac[6] * inv, ac[7] * inv);
    uint4 o;
    o.x = *(uint32_t*)&h0; o.y = *(uint32_t*)&h1;
    o.z = *(uint32_t*)&h2; o.w = *(uint32_t*)&h3;
    ((uint4*)(g_aggh + (size_t)node * D))[lid] = o;
}

// ---------------- fp16 wmma GEMM: BK=128, 2-stage, 1 barrier/chunk ----------------
// CTA tile: 128 rows x 256 cols, 512 threads, warp grid 4m x 4n, warp tile 32x64.
#define BM 128
#define N_TILES (M_PAD / BM)                // 391
#define GEMM_THREADS 512
#define BK 128
#define LDTH 136                            // 128 + 8 pad (272B: 4-bank row skew)
#define A_TILE_H (BM * LDTH)                // 17408 halfs
#define B_TILE_H (256 * LDTH)               // 34816 halfs
#define STAGE_H (A_TILE_H + B_TILE_H)       // 52224 halfs (104448 B)
#define GEMM_SMEM (2 * STAGE_H * 2)         // 208896 bytes
#define C_STRIDE 264                        // fp32 C-tile row stride in smem

__global__ void __launch_bounds__(GEMM_THREADS)
k_gemm(int sel, int layer) {
    extern __shared__ __half smh[];
    const __half* __restrict__ xcur =
        (sel < 0) ? g_x0h : (sel == 0 ? g_xah : g_xbh);
    const __half* __restrict__ WTh = g_WTh + (size_t)layer * D * K2;
    const int tid = threadIdx.x;
    const int wid = tid >> 5;
    const int m0 = blockIdx.x * BM;
    const uint32_t smem_b = smem_u32(smh);

    const int warp_m = wid & 3;   // 4 warps over 128 rows (32 each)
    const int warp_n = wid >> 2;  // 4 warps over 256 cols (64 each)

    wmma::fragment<wmma::accumulator, 16, 16, 16, float> c[2][4];
    #pragma unroll
    for (int i = 0; i < 2; i++)
        #pragma unroll
        for (int j = 0; j < 4; j++)
            wmma::fill_fragment(c[i][j], 0.0f);

    auto load_chunk = [&](int kc) {
        const int s = kc & 1;
        __half* As = smh + s * STAGE_H;
        __half* Bs = As + A_TILE_H;
        const __half* __restrict__ Asrc = (kc < 2) ? g_aggh : xcur;
        const int ka = (kc & 1) * BK;
        const int kb = kc * BK;
        // A: 128 rows x 16 quads = 2048 quads, 4/thread
        #pragma unroll
        for (int i = 0; i < 4; i++) {
            int idx = tid + GEMM_THREADS * i;
            int row = idx >> 4, q = idx & 15;
            int gr = m0 + row;
            bool v = gr < N_NODES;
            cp16(smem_b + (uint32_t)((As - smh) + row * LDTH + q * 8) * 2,
                 Asrc + (size_t)(v ? gr : 0) * D + ka + q * 8, v);
        }
        // B: 256 rows x 16 quads = 4096 quads, 8/thread
        #pragma unroll
        for (int i = 0; i < 8; i++) {
            int idx = tid + GEMM_THREADS * i;
            int row = idx >> 4, q = idx & 15;
            cp16(smem_b + (uint32_t)((Bs - smh) + row * LDTH + q * 8) * 2,
                 WTh + (size_t)row * K2 + kb + q * 8, true);
        }
        asm volatile("cp.async.commit_group;" ::: "memory");
    };

    // 2-stage ring, ONE barrier per chunk:
    //   wait(load kc) -> barrier (also: everyone done computing kc-1, so
    //   stage (kc+1)%2 == (kc-1)%2 is free) -> issue load kc+1 -> compute kc.
    load_chunk(0);
    for (int kc = 0; kc < 4; kc++) {
        asm volatile("cp.async.wait_group 0;" ::: "memory");
        __syncthreads();
        if (kc + 1 < 4) load_chunk(kc + 1);
        const __half* As = smh + (kc & 1) * STAGE_H;
        const __half* Bs = As + A_TILE_H;
        #pragma unroll
        for (int kk = 0; kk < 8; kk++) {
            wmma::fragment<wmma::matrix_a, 16, 16, 16, __half,
                           wmma::row_major> a[2];
            #pragma unroll
            for (int i = 0; i < 2; i++)
                wmma::load_matrix_sync(
                    a[i], As + (warp_m * 32 + i * 16) * LDTH + kk * 16, LDTH);
            #pragma unroll
            for (int j = 0; j < 4; j++) {
                wmma::fragment<wmma::matrix_b, 16, 16, 16, __half,
                               wmma::col_major> b;
                wmma::load_matrix_sync(
                    b, Bs + (warp_n * 64 + j * 16) * LDTH + kk * 16, LDTH);
                wmma::mma_sync(c[0][j], a[0], b, c[0][j]);
                wmma::mma_sync(c[1][j], a[1], b, c[1][j]);
            }
        }
    }

    // ---- epilogue: C -> smem (two 64-row halves) -> h16 + column sums ----
    float* Cs = (float*)smh;
    float* red = Cs + 64 * C_STRIDE;
    const int col = tid & 255;
    const int rh = tid >> 8;
    float s = 0.f, s2 = 0.f;
    #pragma unroll
    for (int half = 0; half < 2; half++) {
        __syncthreads();
        if ((warp_m >> 1) == half) {
            int lrow = (warp_m & 1) * 32;
            #pragma unroll
            for (int i = 0; i < 2; i++)
                #pragma unroll
                for (int j = 0; j < 4; j++)
                    wmma::store_matrix_sync(
                        Cs + (lrow + i * 16) * C_STRIDE + warp_n * 64 + j * 16,
                        c[i][j], C_STRIDE, wmma::mem_row_major);
        }
        __syncthreads();
        #pragma unroll 4
        for (int r = 0; r < 32; r++) {
            float v = Cs[(rh * 32 + r) * C_STRIDE + col];
            s += v;
            s2 += v * v;
            g_h16[(size_t)(m0 + half * 64 + rh * 32 + r) * D + col] =
                __float2half(v);
        }
    }
    __syncthreads();
    if (rh == 1) { red[col] = s; red[256 + col] = s2; }
    __syncthreads();
    if (rh == 0) {
        s += red[col];
        s2 += red[256 + col];
        atomicAdd(&g_sums[layer][col], s);
        atomicAdd(&g_sums[layer][D + col], s2);
    }
}

// ---------------- normalize (+ inlined BN finalize per block) ----------------
__device__ __forceinline__ void compute_ss(float* ss, int layer,
                                           const float* __restrict__ gamma,
                                           const float* __restrict__ beta) {
    int c = threadIdx.x;
    if (c < D) {
        float mu = g_sums[layer][c] * (1.0f / N_NODES);
        float var = g_sums[layer][D + c] * (1.0f / N_NODES) - mu * mu;
        float rs = rsqrtf(var + BN_EPS);
        float sc = gamma[c] * rs;
        ss[c] = sc;
        ss[D + c] = beta[c] - mu * sc;   // bias bl cancels in BN exactly
    }
}

__global__ void k_norm_h(int layer, int sel_out,
                         const float* __restrict__ gamma,
                         const float* __restrict__ beta) {
    __half* __restrict__ out = (sel_out == 0) ? g_xah : g_xbh;
    __shared__ float ss[2 * D];
    compute_ss(ss, layer, gamma, beta);
    __syncthreads();
    const int total = N_NODES * D / 8;
    const uint4* hp = (const uint4*)g_h16;
    for (int i = blockIdx.x * blockDim.x + threadIdx.x; i < total;
         i += gridDim.x * blockDim.x) {
        int c = (i & 31) * 8;
        uint4 u = hp[i];
        __half2* up = (__half2*)&u;
        uint4 o;
        __half2* op = (__half2*)&o;
        #pragma unroll
        for (int j = 0; j < 4; j++) {
            float2 f = __half22float2(up[j]);
            float r0 = fmaxf(fmaf(f.x, ss[c + 2 * j], ss[D + c + 2 * j]), 0.f);
            float r1 = fmaxf(fmaf(f.y, ss[c + 2 * j + 1], ss[D + c + 2 * j + 1]), 0.f);
            op[j] = __floats2half2_rn(r0, r1);
        }
        ((uint4*)out)[i] = o;
    }
}

__global__ void k_norm_f(int layer, const float* __restrict__ gamma,
                         const float* __restrict__ beta,
                         float* __restrict__ out) {
    __shared__ float ss[2 * D];
    compute_ss(ss, layer, gamma, beta);
    __syncthreads();
    const int total = N_NODES * D / 4;
    const uint2* hp = (const uint2*)g_h16;
    for (int i = blockIdx.x * blockDim.x + threadIdx.x; i < total;
         i += gridDim.x * blockDim.x) {
        int c = (i & (D / 4 - 1)) * 4;
        uint2 u = hp[i];
        __half2* up = (__half2*)&u;
        float2 f0 = __half22float2(up[0]);
        float2 f1 = __half22float2(up[1]);
        float4 r;
        r.x = fmaxf(fmaf(f0.x, ss[c + 0], ss[D + c + 0]), 0.f);
        r.y = fmaxf(fmaf(f0.y, ss[c + 1], ss[D + c + 1]), 0.f);
        r.z = fmaxf(fmaf(f1.x, ss[c + 2], ss[D + c + 2]), 0.f);
        r.w = fmaxf(fmaf(f1.y, ss[c + 3], ss[D + c + 3]), 0.f);
        ((float4*)out)[i] = r;
    }
}

// ---------------- launch ----------------
extern "C" void kernel_launch(void* const* d_in, const int* in_sizes, int n_in,
                              void* d_out, int out_size) {
    const float* x     = (const float*)d_in[0];
    const float* Wl    = (const float*)d_in[1];
    // d_in[2] = bl: cancelled exactly by BatchNorm, unused.
    const float* Wr    = (const float*)d_in[3];
    const float* gamma = (const float*)d_in[4];
    const float* beta  = (const float*)d_in[5];
    const int*   ei    = (const int*)d_in[6];   // int32 (JAX x64 disabled)
    float* out = (float*)d_out;

    cudaFuncSetAttribute(k_gemm, cudaFuncAttributeMaxDynamicSharedMemorySize,
                         GEMM_SMEM);

    const int* srcp = ei;
    const int* dstp = ei + N_EDGES;

    k_count<<<(N_EDGES + 255) / 256, 256>>>(dstp);
    k_scan_scat<<<(N_EDGES + 1023) / 1024, 1024>>>(srcp, dstp, x, Wl, Wr);

    int cur_sel = -1;
    for (int l = 0; l < NL; l++) {
        k_agg<<<(N_NODES + 7) / 8, 256>>>(cur_sel, l);
        k_gemm<<<N_TILES, GEMM_THREADS, GEMM_SMEM>>>(cur_sel, l);
        if (l < NL - 1) {
            int out_sel = (l == 0) ? 0 : 1;
            k_norm_h<<<6250, 256>>>(l, out_sel, gamma + (size_t)l * D,
                                    beta + (size_t)l * D);
            cur_sel = out_sel;
        } else {
            k_norm_f<<<12500, 256>>>(l, gamma + (size_t)l * D,
                                     beta + (size_t)l * D, out);
        }
    }
}

// round 14
// speedup vs baseline: 1.0317x; 1.0317x over previous
#include <cuda_runtime.h>
#include <cuda_fp16.h>
#include <mma.h>
#include <cstdint>

using namespace nvcuda;

#define N_NODES 50000
#define M_PAD 50048
#define N_EDGES 800000
#define D 256
#define K2 512
#define NL 3
#define BN_EPS 1e-5f

// ---------------- device scratch ----------------
// Cross-call invariants: g_deg == 0 at k_scan_scat entry (module-load zero on
// first call; scan re-zeroes after consuming); g_flag reset by k_count.
// g_sums slot (l+2)%3 fully re-zeroed by k_agg(l) block 0 after its last
// reader retired in stream order.
__device__ int    g_deg[N_NODES];
__device__ int    g_rowptr[N_NODES + 1];
__device__ int    g_cursor[N_NODES];
__device__ int    g_csr[N_EDGES];
__device__ volatile int g_flag;
__device__ __half g_x0h[(size_t)M_PAD * D];
__device__ __half g_xah[(size_t)M_PAD * D];
__device__ __half g_xbh[(size_t)M_PAD * D];
__device__ __half g_aggh[(size_t)M_PAD * D];
__device__ __half g_WTh[(size_t)NL * D * K2]; // [layer][n][k] B^T, K-major, fp16
__device__ __half g_h16[(size_t)M_PAD * D];   // pre-BN activations (fp16)
__device__ float  g_sums[NL][2 * D];

// ---------------- helpers ----------------
__device__ __forceinline__ uint32_t smem_u32(const void* p) {
    uint32_t a;
    asm("{ .reg .u64 t; cvta.to.shared.u64 t, %1; cvt.u32.u64 %0, t; }"
        : "=r"(a) : "l"(p));
    return a;
}

__device__ __forceinline__ void cp16(uint32_t dst, const void* src, bool valid) {
    int sz = valid ? 16 : 0;   // sz=0 -> 16-byte zero-fill
    asm volatile("cp.async.cg.shared.global [%0], [%1], 16, %2;"
                 :: "r"(dst), "l"(src), "r"(sz) : "memory");
}

__device__ __forceinline__ void acc8(float* ac, uint4 u) {
    __half2* hp = (__half2*)&u;
    #pragma unroll
    for (int j = 0; j < 4; j++) {
        float2 f = __half22float2(hp[j]);
        ac[2 * j] += f.x;
        ac[2 * j + 1] += f.y;
    }
}

// ---------------- CSR: count (also resets spin flag) ----------------
__global__ void k_count(const int* __restrict__ dst) {
    if (blockIdx.x == 0 && threadIdx.x == 0) g_flag = 0;
    int e = blockIdx.x * blockDim.x + threadIdx.x;
    if (e < N_EDGES) {
        int d = dst[e];
        if (d >= 0 && d < N_NODES) atomicAdd(&g_deg[d], 1);
    }
}

// ---------------- scan (block 0) + spin gate + scatter + cast + transpose ----------------
#define SCAN_C 49
__global__ void __launch_bounds__(1024)
k_scan_scat(const int* __restrict__ src, const int* __restrict__ dst,
            const float* __restrict__ x,
            const float* __restrict__ Wl, const float* __restrict__ Wr) {
    int t = threadIdx.x;
    if (blockIdx.x == 0) {
        int lane = t & 31, w = t >> 5;
        int base = t * SCAN_C;
        int lim = min(base + SCAN_C, N_NODES);
        int sum = 0;
        for (int i = base; i < lim; i++) sum += g_deg[i];
        int v = sum;
        #pragma unroll
        for (int o = 1; o < 32; o <<= 1) {
            int n = __shfl_up_sync(0xffffffffu, v, o);
            if (lane >= o) v += n;
        }
        __shared__ int wt[32];
        if (lane == 31) wt[w] = v;
        __syncthreads();
        if (w == 0) {
            int xv = wt[lane];
            #pragma unroll
            for (int o = 1; o < 32; o <<= 1) {
                int n = __shfl_up_sync(0xffffffffu, xv, o);
                if (lane >= o) xv += n;
            }
            wt[lane] = xv;
        }
        __syncthreads();
        int excl = v - sum + (w > 0 ? wt[w - 1] : 0);
        int run = excl;
        for (int i = base; i < lim; i++) {
            int d = g_deg[i];
            g_rowptr[i] = run;
            g_cursor[i] = run;
            run += d;
            g_deg[i] = 0;
        }
        if (t == 1023) g_rowptr[N_NODES] = run;
        __threadfence();
        __syncthreads();
        if (t == 0) g_flag = 1;
    } else {
        if (t == 0) {
            while (g_flag == 0) __nanosleep(100);
        }
    }
    __syncthreads();
    __threadfence();

    int gtid = blockIdx.x * 1024 + t;
    int stride = gridDim.x * 1024;
    if (gtid < N_EDGES) {
        int d = dst[gtid];
        int sv = src[gtid];
        if (d >= 0 && d < N_NODES && sv >= 0 && sv < N_NODES) {
            int pos = atomicAdd(&g_cursor[d], 1);
            g_csr[pos] = sv;
        }
    }
    const float4* xp = (const float4*)x;
    for (int i = gtid; i < N_NODES * D / 8; i += stride) {
        float4 a = xp[2 * i], b = xp[2 * i + 1];
        __half2 h0 = __floats2half2_rn(a.x, a.y);
        __half2 h1 = __floats2half2_rn(a.z, a.w);
        __half2 h2 = __floats2half2_rn(b.x, b.y);
        __half2 h3 = __floats2half2_rn(b.z, b.w);
        uint4 o;
        o.x = *(uint32_t*)&h0; o.y = *(uint32_t*)&h1;
        o.z = *(uint32_t*)&h2; o.w = *(uint32_t*)&h3;
        ((uint4*)g_x0h)[i] = o;
    }
    for (int i = gtid; i < NL * D * K2; i += stride) {
        int l = i / (D * K2);
        int r = i % (D * K2);
        int n = r / K2, k = r % K2;
        float v = (k < D) ? Wl[(size_t)l * D * D + (size_t)k * D + n]
                          : Wr[(size_t)l * D * D + (size_t)(k - D) * D + n];
        g_WTh[i] = __float2half(v);
    }
}

// ---------------- mean aggregation: one WARP per node, edge-unroll 4 ----------------
__global__ void __launch_bounds__(256)
k_agg(int sel, int layer) {
    const __half* __restrict__ xcur =
        (sel < 0) ? g_x0h : (sel == 0 ? g_xah : g_xbh);
    const int tid = threadIdx.x;
    const int wid = tid >> 5, lid = tid & 31;

    if (blockIdx.x == 0) {
        g_sums[(layer + 2) % NL][tid] = 0.f;
        g_sums[(layer + 2) % NL][tid + 256] = 0.f;
    }

    int node = blockIdx.x * 8 + wid;
    if (node >= N_NODES) return;
    int beg = g_rowptr[node], end = g_rowptr[node + 1];
    float ac[8] = {0.f, 0.f, 0.f, 0.f, 0.f, 0.f, 0.f, 0.f};
    int e = beg;
    for (; e + 3 < end; e += 4) {
        int s0 = g_csr[e], s1 = g_csr[e + 1], s2 = g_csr[e + 2], s3 = g_csr[e + 3];
        uint4 u0 = ((const uint4*)(xcur + (size_t)s0 * D))[lid];
        uint4 u1 = ((const uint4*)(xcur + (size_t)s1 * D))[lid];
        uint4 u2 = ((const uint4*)(xcur + (size_t)s2 * D))[lid];
        uint4 u3 = ((const uint4*)(xcur + (size_t)s3 * D))[lid];
        acc8(ac, u0); acc8(ac, u1); acc8(ac, u2); acc8(ac, u3);
    }
    for (; e < end; e++) {
        uint4 u = ((const uint4*)(xcur + (size_t)g_csr[e] * D))[lid];
        acc8(ac, u);
    }
    float inv = 1.0f / fmaxf((float)(end - beg), 1.0f);
    __half2 h0 = __floats2half2_rn(ac[0] * inv, ac[1] * inv);
    __half2 h1 = __floats2half2_rn(ac[2] * inv, ac[3] * inv);
    __half2 h2 = __floats2half2_rn(ac[4] * inv, ac[5] * inv);
    __half2 h3 = __floats2half2_rn(ac[6] * inv, ac[7] * inv);
    uint4 o;
    o.x = *(uint32_t*)&h0; o.y = *(uint32_t*)&h1;
    o.z = *(uint32_t*)&h2; o.w = *(uint32_t*)&h3;
    ((uint4*)(g_aggh + (size_t)node * D))[lid] = o;
}

// ---------------- fp16 wmma GEMM: 128x128 tile, 2 CTAs/SM, 3-stage ----------------
// 256 threads, warp grid 4m x 2n, warp tile 32x64. Grid (391, 2).
#define BM 128
#define BN 128
#define N_TILES (M_PAD / BM)                // 391
#define GEMM_THREADS 256
#define LDTH 72
#define A_TILE_H (BM * LDTH)                // 9216 halfs
#define B_TILE_H (BN * LDTH)                // 9216 halfs
#define STAGE_H (A_TILE_H + B_TILE_H)       // 18432 halfs (36864 B)
#define GEMM_SMEM (3 * STAGE_H * 2)         // 110592 bytes (fits 2/SM)
#define C_STRIDE 132                        // fp32 C-tile row stride in smem

__global__ void __launch_bounds__(GEMM_THREADS, 2)
k_gemm(int sel, int layer) {
    extern __shared__ __half smh[];
    const __half* __restrict__ xcur =
        (sel < 0) ? g_x0h : (sel == 0 ? g_xah : g_xbh);
    const __half* __restrict__ WTh = g_WTh + (size_t)layer * D * K2;
    const int tid = threadIdx.x;
    const int wid = tid >> 5;
    const int m0 = blockIdx.x * BM;
    const int n0 = blockIdx.y * BN;
    const uint32_t smem_b = smem_u32(smh);

    const int warp_m = wid & 3;   // 4 warps over 128 rows (32 each)
    const int warp_n = wid >> 2;  // 2 warps over 128 cols (64 each)

    wmma::fragment<wmma::accumulator, 16, 16, 16, float> c[2][4];
    #pragma unroll
    for (int i = 0; i < 2; i++)
        #pragma unroll
        for (int j = 0; j < 4; j++)
            wmma::fill_fragment(c[i][j], 0.0f);

    auto load_chunk = [&](int kc) {
        const int s = kc % 3;
        __half* As = smh + s * STAGE_H;
        __half* Bs = As + A_TILE_H;
        const __half* __restrict__ Asrc = (kc < 4) ? g_aggh : xcur;
        const int ka = (kc & 3) * 64;
        const int kb = kc * 64;
        // A: 128 rows x 8 quads = 1024 quads, 4/thread
        #pragma unroll
        for (int i = 0; i < 4; i++) {
            int idx = tid + GEMM_THREADS * i;
            int row = idx >> 3, q = idx & 7;
            int gr = m0 + row;
            bool v = gr < N_NODES;
            cp16(smem_b + (uint32_t)((As - smh) + row * LDTH + q * 8) * 2,
                 Asrc + (size_t)(v ? gr : 0) * D + ka + q * 8, v);
        }
        // B: 128 rows x 8 quads = 1024 quads, 4/thread
        #pragma unroll
        for (int i = 0; i < 4; i++) {
            int idx = tid + GEMM_THREADS * i;
            int row = idx >> 3, q = idx & 7;
            cp16(smem_b + (uint32_t)((Bs - smh) + row * LDTH + q * 8) * 2,
                 WTh + (size_t)(n0 + row) * K2 + kb + q * 8, true);
        }
        asm volatile("cp.async.commit_group;" ::: "memory");
    };

    load_chunk(0);
    for (int kc = 0; kc < 8; kc++) {
        if (kc + 1 < 8) {
            load_chunk(kc + 1);
            asm volatile("cp.async.wait_group 1;" ::: "memory");
        } else {
            asm volatile("cp.async.wait_group 0;" ::: "memory");
        }
        __syncthreads();   // 3-stage ring: write target never collides
        const __half* As = smh + (kc % 3) * STAGE_H;
        const __half* Bs = As + A_TILE_H;
        #pragma unroll
        for (int kk = 0; kk < 4; kk++) {
            wmma::fragment<wmma::matrix_a, 16, 16, 16, __half,
                           wmma::row_major> a[2];
            #pragma unroll
            for (int i = 0; i < 2; i++)
                wmma::load_matrix_sync(
                    a[i], As + (warp_m * 32 + i * 16) * LDTH + kk * 16, LDTH);
            #pragma unroll
            for (int j = 0; j < 4; j++) {
                wmma::fragment<wmma::matrix_b, 16, 16, 16, __half,
                               wmma::col_major> b;
                wmma::load_matrix_sync(
                    b, Bs + (warp_n * 64 + j * 16) * LDTH + kk * 16, LDTH);
                wmma::mma_sync(c[0][j], a[0], b, c[0][j]);
                wmma::mma_sync(c[1][j], a[1], b, c[1][j]);
            }
        }
    }

    // ---- epilogue: C -> smem (two 64-row halves) -> h16 + column sums ----
    // Pad rows of A are zero-filled -> C pad rows are exactly 0 -> sums safe.
    float* Cs = (float*)smh;                 // 64 x C_STRIDE fp32
    float* red = Cs + 64 * C_STRIDE;         // 256 floats reduction buffer
    const int col = tid & 127;               // local column 0..127
    const int rh = tid >> 7;                 // 0/1: 32-row slice within half
    float s = 0.f, s2 = 0.f;
    #pragma unroll
    for (int half = 0; half < 2; half++) {
        __syncthreads();
        if ((warp_m >> 1) == half) {         // warps owning rows of this half
            int lrow = (warp_m & 1) * 32;
            #pragma unroll
            for (int i = 0; i < 2; i++)
                #pragma unroll
                for (int j = 0; j < 4; j++)
                    wmma::store_matrix_sync(
                        Cs + (lrow + i * 16) * C_STRIDE + warp_n * 64 + j * 16,
                        c[i][j], C_STRIDE, wmma::mem_row_major);
        }
        __syncthreads();
        #pragma unroll 4
        for (int r = 0; r < 32; r++) {
            float v = Cs[(rh * 32 + r) * C_STRIDE + col];
            s += v;
            s2 += v * v;
            g_h16[(size_t)(m0 + half * 64 + rh * 32 + r) * D + n0 + col] =
                __float2half(v);
        }
    }
    __syncthreads();
    if (rh == 1) { red[col] = s; red[128 + col] = s2; }
    __syncthreads();
    if (rh == 0) {
        s += red[col];
        s2 += red[128 + col];
        atomicAdd(&g_sums[layer][n0 + col], s);
        atomicAdd(&g_sums[layer][D + n0 + col], s2);
    }
}

// ---------------- normalize (+ inlined BN finalize per block) ----------------
__device__ __forceinline__ void compute_ss(float* ss, int layer,
                                           const float* __restrict__ gamma,
                                           const float* __restrict__ beta) {
    int c = threadIdx.x;
    if (c < D) {
        float mu = g_sums[layer][c] * (1.0f / N_NODES);
        float var = g_sums[layer][D + c] * (1.0f / N_NODES) - mu * mu;
        float rs = rsqrtf(var + BN_EPS);
        float sc = gamma[c] * rs;
        ss[c] = sc;
        ss[D + c] = beta[c] - mu * sc;   // bias bl cancels in BN exactly
    }
}

__global__ void k_norm_h(int layer, int sel_out,
                         const float* __restrict__ gamma,
                         const float* __restrict__ beta) {
    __half* __restrict__ out = (sel_out == 0) ? g_xah : g_xbh;
    __shared__ float ss[2 * D];
    compute_ss(ss, layer, gamma, beta);
    __syncthreads();
    const int total = N_NODES * D / 8;
    const uint4* hp = (const uint4*)g_h16;
    for (int i = blockIdx.x * blockDim.x + threadIdx.x; i < total;
         i += gridDim.x * blockDim.x) {
        int c = (i & 31) * 8;
        uint4 u = hp[i];
        __half2* up = (__half2*)&u;
        uint4 o;
        __half2* op = (__half2*)&o;
        #pragma unroll
        for (int j = 0; j < 4; j++) {
            float2 f = __half22float2(up[j]);
            float r0 = fmaxf(fmaf(f.x, ss[c + 2 * j], ss[D + c + 2 * j]), 0.f);
            float r1 = fmaxf(fmaf(f.y, ss[c + 2 * j + 1], ss[D + c + 2 * j + 1]), 0.f);
            op[j] = __floats2half2_rn(r0, r1);
        }
        ((uint4*)out)[i] = o;
    }
}

__global__ void k_norm_f(int layer, const float* __restrict__ gamma,
                         const float* __restrict__ beta,
                         float* __restrict__ out) {
    __shared__ float ss[2 * D];
    compute_ss(ss, layer, gamma, beta);
    __syncthreads();
    const int total = N_NODES * D / 4;
    const uint2* hp = (const uint2*)g_h16;
    for (int i = blockIdx.x * blockDim.x + threadIdx.x; i < total;
         i += gridDim.x * blockDim.x) {
        int c = (i & (D / 4 - 1)) * 4;
        uint2 u = hp[i];
        __half2* up = (__half2*)&u;
        float2 f0 = __half22float2(up[0]);
        float2 f1 = __half22float2(up[1]);
        float4 r;
        r.x = fmaxf(fmaf(f0.x, ss[c + 0], ss[D + c + 0]), 0.f);
        r.y = fmaxf(fmaf(f0.y, ss[c + 1], ss[D + c + 1]), 0.f);
        r.z = fmaxf(fmaf(f1.x, ss[c + 2], ss[D + c + 2]), 0.f);
        r.w = fmaxf(fmaf(f1.y, ss[c + 3], ss[D + c + 3]), 0.f);
        ((float4*)out)[i] = r;
    }
}

// ---------------- launch ----------------
extern "C" void kernel_launch(void* const* d_in, const int* in_sizes, int n_in,
                              void* d_out, int out_size) {
    const float* x     = (const float*)d_in[0];
    const float* Wl    = (const float*)d_in[1];
    // d_in[2] = bl: cancelled exactly by BatchNorm, unused.
    const float* Wr    = (const float*)d_in[3];
    const float* gamma = (const float*)d_in[4];
    const float* beta  = (const float*)d_in[5];
    const int*   ei    = (const int*)d_in[6];   // int32 (JAX x64 disabled)
    float* out = (float*)d_out;

    cudaFuncSetAttribute(k_gemm, cudaFuncAttributeMaxDynamicSharedMemorySize,
                         GEMM_SMEM);

    const int* srcp = ei;
    const int* dstp = ei + N_EDGES;

    k_count<<<(N_EDGES + 255) / 256, 256>>>(dstp);
    k_scan_scat<<<(N_EDGES + 1023) / 1024, 1024>>>(srcp, dstp, x, Wl, Wr);

    int cur_sel = -1;
    for (int l = 0; l < NL; l++) {
        k_agg<<<(N_NODES + 7) / 8, 256>>>(cur_sel, l);
        dim3 gg(N_TILES, 2);
        k_gemm<<<gg, GEMM_THREADS, GEMM_SMEM>>>(cur_sel, l);
        if (l < NL - 1) {
            int out_sel = (l == 0) ? 0 : 1;
            k_norm_h<<<6250, 256>>>(l, out_sel, gamma + (size_t)l * D,
                                    beta + (size_t)l * D);
            cur_sel = out_sel;
        } else {
            k_norm_f<<<12500, 256>>>(l, gamma + (size_t)l * D,
                                     beta + (size_t)l * D, out);
        }
    }
}